// round 15
// baseline (speedup 1.0000x reference)
#include <cuda_runtime.h>
#include <math.h>

// ChamferLoss: B=4, N=8192, K=8 nearest neighbors, L2 norm.
// loss = mean over all (query, knn) exact distances, both directions.
//
// R15 = R6 mainloop (QPT=2 packed f32x2 queries, smem-tiled candidates)
//     + NSPLIT=4 interleaved candidate parity (4096 warps = 27.7/SM,
//       every split warm-starts from the rank-aligned tile)
//     + R14 exact window (analytic bucket edges, one threshold reduce).

namespace {
constexpr int   B_     = 4;
constexpr int   N_     = 8192;
constexpr int   KNN    = 8;
constexpr int   NSETS  = B_ * 2;             // b*2+s: s=0 pred(src+flow), s=1 tgt
constexpr int   NBUCK  = 256;
constexpr float BUCKW  = 0.0625f;            // 1/16 over [-8, 8)
constexpr int   TS     = 1024;               // global candidates per tile
constexpr int   NCH    = N_ / TS;            // 8 tiles
constexpr int   SPT    = TS / 4;             // 256 split-candidates per tile
constexpr int   KT     = 128;                // knn threads
constexpr int   QPT    = 2;                  // queries per thread
constexpr int   QPB    = KT * QPT;           // 256 queries per block
constexpr int   QCH    = N_ / QPB;           // 32 query chunks per set
constexpr int   NSPLIT = 4;                  // candidate index mod 4
constexpr int   KBLK   = NSETS * QCH * NSPLIT;  // 1024 knn blocks
constexpr int   NQTOT  = NSETS * N_;         // 65536 query slots
constexpr int   MBLOCKS = NQTOT / 256;       // 256 merge blocks
}

typedef unsigned long long ull;

__device__ __forceinline__ ull fx2_add(ull a, ull b) {
    ull r; asm("add.rn.f32x2 %0, %1, %2;" : "=l"(r) : "l"(a), "l"(b)); return r;
}
__device__ __forceinline__ ull fx2_mul(ull a, ull b) {
    ull r; asm("mul.rn.f32x2 %0, %1, %2;" : "=l"(r) : "l"(a), "l"(b)); return r;
}
__device__ __forceinline__ ull fx2_fma(ull a, ull b, ull c) {
    ull r; asm("fma.rn.f32x2 %0, %1, %2, %3;" : "=l"(r) : "l"(a), "l"(b), "l"(c)); return r;
}
__device__ __forceinline__ ull pack2(float lo, float hi) {
    return (ull)__float_as_uint(lo) | ((ull)__float_as_uint(hi) << 32);
}
__device__ __forceinline__ ull dupf(float v) {
    unsigned u = __float_as_uint(v);
    return (ull)u | ((ull)u << 32);
}
__device__ __forceinline__ int quant8(float x) {
    float q = (x + 8.0f) * 16.0f;
    q = fminf(fmaxf(q, 0.0f), 255.0f);
    return (int)q;
}

// Scratch (static device globals: no allocation).
__device__ float g_px[NSETS][N_];        // bucket-sorted coordinates, SoA
__device__ float g_py[NSETS][N_];
__device__ float g_pz[NSETS][N_];
__device__ float g_knn[NSPLIT][NQTOT][KNN];  // per-split sorted partial d^2
__device__ float g_partials[MBLOCKS];

// ---------- deterministic counting sort by x-bucket (1 block per set) ------
__global__ __launch_bounds__(1024)
void bucket_sort_kernel(const float* __restrict__ src,
                        const float* __restrict__ tgt,
                        const float* __restrict__ flow)
{
    __shared__ unsigned short wcnt[32][NBUCK];   // per-warp per-bucket (16 KB)
    __shared__ unsigned       bstart[NBUCK];
    __shared__ unsigned       tot[NBUCK];

    const int set = blockIdx.x;
    const int b   = set >> 1;
    const int s   = set & 1;
    const float* __restrict__ sb = src  + (size_t)b * N_ * 3;
    const float* __restrict__ tb = tgt  + (size_t)b * N_ * 3;
    const float* __restrict__ fb = flow + (size_t)b * N_ * 3;

    const int tid  = threadIdx.x;
    const int w    = tid >> 5;
    const int lane = tid & 31;
    const unsigned below = (1u << lane) - 1u;

    for (int i = tid; i < 32 * NBUCK; i += 1024)
        (&wcnt[0][0])[i] = 0;
    __syncthreads();

    // pass 1: count (leader-per-key non-atomic adds; order fixed)
    float xr[8];
#pragma unroll
    for (int it = 0; it < 8; ++it) {
        const int i = it * 1024 + tid;
        const float x = (s == 0) ? (sb[3 * i] + fb[3 * i]) : tb[3 * i];
        xr[it] = x;
        const int key = quant8(x);
        const unsigned mask = __match_any_sync(0xffffffffu, key);
        if ((mask & below) == 0u)   // leader lane for this key
            wcnt[w][key] = (unsigned short)(wcnt[w][key] + __popc(mask));
        __syncwarp();
    }
    __syncthreads();

    // per-bucket exclusive scan over warps (thread t owns bucket t)
    unsigned mytot = 0;
    if (tid < NBUCK) {
        unsigned run = 0;
        for (int ww = 0; ww < 32; ++ww) {
            const unsigned c = wcnt[ww][tid];
            wcnt[ww][tid] = (unsigned short)run;
            run += c;
        }
        tot[tid] = run; mytot = run;
    }
    __syncthreads();
    // inclusive scan of bucket totals
    for (int d = 1; d < NBUCK; d <<= 1) {
        unsigned v = 0;
        if (tid < NBUCK && tid >= d) v = tot[tid - d];
        __syncthreads();
        if (tid < NBUCK) tot[tid] += v;
        __syncthreads();
    }
    if (tid < NBUCK) bstart[tid] = tot[tid] - mytot;
    __syncthreads();

    // pass 2: deterministic scatter (per-warp cursors, lane-rank within key)
#pragma unroll
    for (int it = 0; it < 8; ++it) {
        const int i = it * 1024 + tid;
        const float x = xr[it];
        const int key = quant8(x);
        const unsigned mask = __match_any_sync(0xffffffffu, key);
        const unsigned r = __popc(mask & below);
        const unsigned basec = wcnt[w][key];
        __syncwarp();
        if (r == 0) wcnt[w][key] = (unsigned short)(basec + __popc(mask));
        __syncwarp();
        const unsigned pos = bstart[key] + basec + r;
        const float y = (s == 0) ? (sb[3 * i + 1] + fb[3 * i + 1]) : tb[3 * i + 1];
        const float z = (s == 0) ? (sb[3 * i + 2] + fb[3 * i + 2]) : tb[3 * i + 2];
        g_px[set][pos] = x; g_py[set][pos] = y; g_pz[set][pos] = z;
    }
}

// ---------- exact windowed KNN, QPT=2, interleaved candidate split ---------
__global__ __launch_bounds__(KT)
void knn_kernel()
{
    __shared__ __align__(16) ulonglong2 sXY[SPT];  // {-x,-x,-y,-y} per cand (4 KB)
    __shared__ __align__(16) ull        sZ[SPT];   // {-z,-z}          (2 KB)
    __shared__ float sred[KT / 32];
    __shared__ float sqmn[KT / 32], sqmx[KT / 32];
    __shared__ float sblo[NCH], sbhi[NCH];

    const int tid  = threadIdx.x;
    const int lane = tid & 31;
    const int wib  = tid >> 5;
    const int bi    = blockIdx.x;
    const int qset  = bi >> 7;                   // 8 sets x (32 chunks x 4 splits)
    const int rem   = bi & 127;
    const int chunk = rem >> 2;                  // 32 query chunks
    const int split = rem & 3;                   // candidate index mod 4
    const int cset  = qset ^ 1;

    // ---- this thread's two queries (bucket-sorted order) ----
    const int slot0 = chunk * QPB + tid;
    const int slot1 = slot0 + KT;
    const float q0x = g_px[qset][slot0], q1x = g_px[qset][slot1];
    const float q0y = g_py[qset][slot0], q1y = g_py[qset][slot1];
    const float q0z = g_pz[qset][slot0], q1z = g_pz[qset][slot1];
    const ull qx2 = pack2(q0x, q1x);
    const ull qy2 = pack2(q0y, q1y);
    const ull qz2 = pack2(q0z, q1z);

    // block query x-range
    float mn = fminf(q0x, q1x), mx = fmaxf(q0x, q1x);
#pragma unroll
    for (int o = 16; o > 0; o >>= 1) {
        mn = fminf(mn, __shfl_xor_sync(0xffffffffu, mn, o));
        mx = fmaxf(mx, __shfl_xor_sync(0xffffffffu, mx, o));
    }
    if (lane == 0) { sqmn[wib] = mn; sqmx[wib] = mx; }

    // analytic tile x-bounds from bucket edges (exact for all cands in tile)
    if (tid < NCH) {
        const int ka = quant8(g_px[cset][tid * TS]);
        const int kb = quant8(g_px[cset][tid * TS + TS - 1]);
        sblo[tid] = (ka == 0)   ? -3.0e38f : ((float)ka * BUCKW - 8.0f);
        sbhi[tid] = (kb == 255) ?  3.0e38f : ((float)(kb + 1) * BUCKW - 8.0f);
    }
    __syncthreads();
    const float xqmin = fminf(fminf(sqmn[0], sqmn[1]), fminf(sqmn[2], sqmn[3]));
    const float xqmax = fmaxf(fmaxf(sqmx[0], sqmx[1]), fmaxf(sqmx[2], sqmx[3]));

    const float* __restrict__ cx = g_px[cset];
    const float* __restrict__ cy = g_py[cset];
    const float* __restrict__ cz = g_pz[cset];

    float h0[KNN], h1[KNN];
#pragma unroll
    for (int i = 0; i < KNN; ++i) { h0[i] = 3.0e38f; h1[i] = 3.0e38f; }
    unsigned t0 = __float_as_uint(3.0e38f);
    unsigned t1 = t0;

    auto scan_tile = [&](int c) {
        __syncthreads();                          // previous tile consumed
        // this split's 256 candidates: indices c*1024 + 4*t + split
        for (int t = tid; t < SPT; t += KT) {
            const int gi = c * TS + 4 * t + split;
            sXY[t].x = dupf(-cx[gi]);
            sXY[t].y = dupf(-cy[gi]);
            sZ[t]    = dupf(-cz[gi]);
        }
        __syncthreads();
#pragma unroll 4
        for (int j = 0; j < SPT; ++j) {
            const ulonglong2 cxy = sXY[j];        // broadcast LDS.128
            const ull cz2 = sZ[j];                // broadcast LDS.64
            const ull dx = fx2_add(qx2, cxy.x);
            const ull dy = fx2_add(qy2, cxy.y);
            const ull dz = fx2_add(qz2, cz2);
            const ull d2 = fx2_fma(dx, dx, fx2_fma(dy, dy, fx2_mul(dz, dz)));
            const unsigned d0 = (unsigned)d2;          // query 0
            const unsigned d1 = (unsigned)(d2 >> 32);  // query 1
            if (__builtin_expect(d0 < t0, 0)) {
                float v = __uint_as_float(d0);
#pragma unroll
                for (int i = KNN - 1; i > 0; --i) {
                    const float hp = h0[i - 1];
                    h0[i] = fmaxf(hp, v);
                    v     = fminf(hp, v);
                }
                h0[0] = v;
                t0 = __float_as_uint(h0[KNN - 1]);
            }
            if (__builtin_expect(d1 < t1, 0)) {
                float v = __uint_as_float(d1);
#pragma unroll
                for (int i = KNN - 1; i > 0; --i) {
                    const float hp = h1[i - 1];
                    h1[i] = fmaxf(hp, v);
                    v     = fminf(hp, v);
                }
                h1[0] = v;
                t1 = __float_as_uint(h1[KNN - 1]);
            }
        }
    };

    // 1) rank-aligned tile: warms every split's thresholds with near cands
    const int c0 = chunk >> 2;                    // 32 chunks -> 8 tiles
    scan_tile(c0);

    // 2) ONE block reduce of kth (partial) distances -> fixed exact window
    float t8 = fmaxf(h0[KNN - 1], h1[KNN - 1]);
#pragma unroll
    for (int o = 16; o > 0; o >>= 1)
        t8 = fmaxf(t8, __shfl_xor_sync(0xffffffffu, t8, o));
    if (lane == 0) sred[wib] = t8;
    __syncthreads();
    const float tmax = fmaxf(fmaxf(sred[0], sred[1]), fmaxf(sred[2], sred[3]));
    const float td = sqrtf(tmax);
    const float wlo = xqmin - td, whi = xqmax + td;

    // 3) fixed predicate loop over remaining tiles (block-uniform, exact)
#pragma unroll
    for (int t = 0; t < NCH; ++t) {
        if (t == c0) continue;
        if (sbhi[t] > wlo && sblo[t] < whi) scan_tile(t);
    }

    // ---- write per-split sorted partial lists (d^2, ascending) ----
    const int qg0 = qset * N_ + slot0;
    const int qg1 = qset * N_ + slot1;
    float4* o0 = reinterpret_cast<float4*>(&g_knn[split][qg0][0]);
    float4* o1 = reinterpret_cast<float4*>(&g_knn[split][qg1][0]);
    o0[0] = make_float4(h0[0], h0[1], h0[2], h0[3]);
    o0[1] = make_float4(h0[4], h0[5], h0[6], h0[7]);
    o1[0] = make_float4(h1[0], h1[1], h1[2], h1[3]);
    o1[1] = make_float4(h1[4], h1[5], h1[6], h1[7]);
}

// --- exact branchless merge helpers ---
__device__ __forceinline__ void halver8(const float* __restrict__ a,
                                        const float* __restrict__ b,
                                        float* __restrict__ m)
{
#pragma unroll
    for (int i = 0; i < 8; ++i) m[i] = fminf(a[i], b[7 - i]);
}
__device__ __forceinline__ void bitonic_sort8(float* __restrict__ m)
{
#pragma unroll
    for (int st = 4; st > 0; st >>= 1)
#pragma unroll
        for (int i = 0; i < 8; ++i)
            if ((i & st) == 0) {
                const float lo = fminf(m[i], m[i + st]);
                const float hi = fmaxf(m[i], m[i + st]);
                m[i] = lo; m[i + st] = hi;
            }
}

// Merge 4 sorted partial top-8 lists per query, sum sqrt, deterministic reduce.
__global__ __launch_bounds__(256)
void chamfer_merge_kernel()
{
    const int qg = blockIdx.x * 256 + threadIdx.x;
    float L[NSPLIT][KNN];
#pragma unroll
    for (int sp = 0; sp < NSPLIT; ++sp) {
        const float4* p = reinterpret_cast<const float4*>(&g_knn[sp][qg][0]);
        const float4 v0 = p[0], v1 = p[1];
        L[sp][0] = v0.x; L[sp][1] = v0.y; L[sp][2] = v0.z; L[sp][3] = v0.w;
        L[sp][4] = v1.x; L[sp][5] = v1.y; L[sp][6] = v1.z; L[sp][7] = v1.w;
    }

    float m01[8], m23[8], fin[8];
    halver8(L[0], L[1], m01); bitonic_sort8(m01);
    halver8(L[2], L[3], m23); bitonic_sort8(m23);
    halver8(m01, m23, fin);   // 8 smallest of all 32 (multiset)

    float s = 0.0f;
#pragma unroll
    for (int i = 0; i < 8; ++i) s += sqrtf(fin[i]);

#pragma unroll
    for (int o = 16; o > 0; o >>= 1)
        s += __shfl_down_sync(0xffffffffu, s, o);

    __shared__ float ws[8];
    if ((threadIdx.x & 31) == 0) ws[threadIdx.x >> 5] = s;
    __syncthreads();
    if (threadIdx.x == 0) {
        float t = 0.0f;
#pragma unroll
        for (int i = 0; i < 8; ++i) t += ws[i];
        g_partials[blockIdx.x] = t;
    }
}

// ---------- final deterministic reduction ----------------------------------
__global__ __launch_bounds__(MBLOCKS)
void reduce_kernel(float* __restrict__ out)
{
    const int t = threadIdx.x;
    float v = g_partials[t];
#pragma unroll
    for (int o = 16; o > 0; o >>= 1)
        v += __shfl_down_sync(0xffffffffu, v, o);

    __shared__ float ws[MBLOCKS / 32];
    if ((t & 31) == 0) ws[t >> 5] = v;
    __syncthreads();
    if (t == 0) {
        float s = 0.0f;
#pragma unroll
        for (int i = 0; i < MBLOCKS / 32; ++i) s += ws[i];
        out[0] = s * (1.0f / (float)(B_ * N_ * KNN));
    }
}

extern "C" void kernel_launch(void* const* d_in, const int* in_sizes, int n_in,
                              void* d_out, int out_size)
{
    (void)in_sizes; (void)n_in; (void)out_size;
    const float* src  = (const float*)d_in[0];
    const float* tgt  = (const float*)d_in[1];
    const float* flow = (const float*)d_in[2];
    float* out = (float*)d_out;

    bucket_sort_kernel<<<NSETS, 1024>>>(src, tgt, flow);
    knn_kernel<<<KBLK, KT>>>();
    chamfer_merge_kernel<<<MBLOCKS, 256>>>();
    reduce_kernel<<<1, MBLOCKS>>>(out);
}

// round 16
// speedup vs baseline: 1.1562x; 1.1562x over previous
#include <cuda_runtime.h>
#include <math.h>

// ChamferLoss: B=4, N=8192, K=8 nearest neighbors, L2 norm.
// loss = mean over all (query, knn) exact distances, both directions.
//
// R16 = R9's proven knn engine (brute scan, NSPLIT=4 contiguous quarters,
//       QPT=2 packed f32x2, 4096 warps = 27.7/SM, Morton-coherent lanes)
//     + 9-bit-Morton 512-bucket counting sort (~25us, replaces 76us bitonic)
//     + coalesced SoA tile loads + exact 4-way bitonic merge.

namespace {
constexpr int   B_     = 4;
constexpr int   N_     = 8192;
constexpr int   KNN    = 8;
constexpr int   NSETS  = B_ * 2;             // b*2+s: s=0 pred(src+flow), s=1 tgt
constexpr int   NBUCK  = 512;                // 9-bit morton buckets
constexpr int   KT     = 128;                // knn threads
constexpr int   QPT    = 2;                  // queries per thread
constexpr int   QPB    = KT * QPT;           // 256 queries per block
constexpr int   QCH    = N_ / QPB;           // 32 query chunks per set
constexpr int   NSPLIT = 4;                  // contiguous candidate quarters
constexpr int   CANDS  = N_ / NSPLIT;        // 2048 candidates per block
constexpr int   CHUNK  = 1024;               // candidates per smem tile
constexpr int   NCHUNK = CANDS / CHUNK;      // 2
constexpr int   KBLK   = NSETS * QCH * NSPLIT;  // 1024 knn blocks
constexpr int   NQTOT  = NSETS * N_;         // 65536 query slots
constexpr int   MBLOCKS = NQTOT / 256;       // 256 merge blocks
}

typedef unsigned long long ull;

__device__ __forceinline__ ull fx2_add(ull a, ull b) {
    ull r; asm("add.rn.f32x2 %0, %1, %2;" : "=l"(r) : "l"(a), "l"(b)); return r;
}
__device__ __forceinline__ ull fx2_mul(ull a, ull b) {
    ull r; asm("mul.rn.f32x2 %0, %1, %2;" : "=l"(r) : "l"(a), "l"(b)); return r;
}
__device__ __forceinline__ ull fx2_fma(ull a, ull b, ull c) {
    ull r; asm("fma.rn.f32x2 %0, %1, %2, %3;" : "=l"(r) : "l"(a), "l"(b), "l"(c)); return r;
}
__device__ __forceinline__ ull pack2(float lo, float hi) {
    return (ull)__float_as_uint(lo) | ((ull)__float_as_uint(hi) << 32);
}
__device__ __forceinline__ ull dupf(float v) {
    unsigned u = __float_as_uint(v);
    return (ull)u | ((ull)u << 32);
}
// 3-bit quantizer over [-4,4) and 9-bit Morton interleave x2y2z2 x1y1z1 x0y0z0
__device__ __forceinline__ unsigned quant3(float x) {
    float q = (x + 4.0f);                        // cell = 1.0
    q = fminf(fmaxf(q, 0.0f), 7.0f);
    return (unsigned)q;
}
__device__ __forceinline__ unsigned morton9(float x, float y, float z) {
    const unsigned qx = quant3(x), qy = quant3(y), qz = quant3(z);
    unsigned k = 0;
#pragma unroll
    for (int b = 2; b >= 0; --b)
        k = (k << 3) | (((qx >> b) & 1u) << 2) | (((qy >> b) & 1u) << 1) | ((qz >> b) & 1u);
    return k;                                    // 9 bits
}

// Scratch (static device globals: no allocation).
__device__ float g_px[NSETS][N_];        // morton-bucket-sorted coords, SoA
__device__ float g_py[NSETS][N_];
__device__ float g_pz[NSETS][N_];
__device__ float g_knn[NSPLIT][NQTOT][KNN];  // per-split sorted partial d^2
__device__ float g_partials[MBLOCKS];

// ---------- deterministic counting sort by Morton bucket (1 block/set) -----
__global__ __launch_bounds__(1024)
void bucket_sort_kernel(const float* __restrict__ src,
                        const float* __restrict__ tgt,
                        const float* __restrict__ flow)
{
    __shared__ unsigned short wcnt[32][NBUCK];   // per-warp per-bucket (32 KB)
    __shared__ unsigned       bstart[NBUCK];
    __shared__ unsigned       tot[NBUCK];

    const int set = blockIdx.x;
    const int b   = set >> 1;
    const int s   = set & 1;
    const float* __restrict__ sb = src  + (size_t)b * N_ * 3;
    const float* __restrict__ tb = tgt  + (size_t)b * N_ * 3;
    const float* __restrict__ fb = flow + (size_t)b * N_ * 3;

    const int tid  = threadIdx.x;
    const int w    = tid >> 5;
    const int lane = tid & 31;
    const unsigned below = (1u << lane) - 1u;

    for (int i = tid; i < 32 * NBUCK; i += 1024)
        (&wcnt[0][0])[i] = 0;
    __syncthreads();

    // pass 1: count (leader-per-key non-atomic adds; order fixed)
    float xr[8], yr[8], zr[8];
    int   kr[8];
#pragma unroll
    for (int it = 0; it < 8; ++it) {
        const int i = it * 1024 + tid;
        float x, y, z;
        if (s == 0) {
            x = sb[3 * i + 0] + fb[3 * i + 0];
            y = sb[3 * i + 1] + fb[3 * i + 1];
            z = sb[3 * i + 2] + fb[3 * i + 2];
        } else {
            x = tb[3 * i + 0]; y = tb[3 * i + 1]; z = tb[3 * i + 2];
        }
        xr[it] = x; yr[it] = y; zr[it] = z;
        const int key = (int)morton9(x, y, z);
        kr[it] = key;
        const unsigned mask = __match_any_sync(0xffffffffu, key);
        if ((mask & below) == 0u)   // leader lane for this key
            wcnt[w][key] = (unsigned short)(wcnt[w][key] + __popc(mask));
        __syncwarp();
    }
    __syncthreads();

    // per-bucket exclusive scan over warps (thread t owns bucket t; t<512)
    unsigned mytot = 0;
    if (tid < NBUCK) {
        unsigned run = 0;
        for (int ww = 0; ww < 32; ++ww) {
            const unsigned c = wcnt[ww][tid];
            wcnt[ww][tid] = (unsigned short)run;
            run += c;
        }
        tot[tid] = run; mytot = run;
    }
    __syncthreads();
    // inclusive scan of bucket totals
    for (int d = 1; d < NBUCK; d <<= 1) {
        unsigned v = 0;
        if (tid < NBUCK && tid >= d) v = tot[tid - d];
        __syncthreads();
        if (tid < NBUCK) tot[tid] += v;
        __syncthreads();
    }
    if (tid < NBUCK) bstart[tid] = tot[tid] - mytot;
    __syncthreads();

    // pass 2: deterministic scatter (per-warp cursors, lane-rank within key)
#pragma unroll
    for (int it = 0; it < 8; ++it) {
        const int key = kr[it];
        const unsigned mask = __match_any_sync(0xffffffffu, key);
        const unsigned r = __popc(mask & below);
        const unsigned basec = wcnt[w][key];
        __syncwarp();
        if (r == 0) wcnt[w][key] = (unsigned short)(basec + __popc(mask));
        __syncwarp();
        const unsigned pos = bstart[key] + basec + r;
        g_px[set][pos] = xr[it];
        g_py[set][pos] = yr[it];
        g_pz[set][pos] = zr[it];
    }
}

// ---------- brute-force KNN, Morton-coherent lanes, NSPLIT=4 ---------------
__global__ __launch_bounds__(KT)
void knn_kernel()
{
    __shared__ __align__(16) ulonglong2 sXY[CHUNK];  // {-x,-x,-y,-y} (16 KB)
    __shared__ __align__(16) ull        sZ[CHUNK];   // {-z,-z}        (8 KB)

    const int tid    = threadIdx.x;
    const int bi     = blockIdx.x;
    const int split  = bi & (NSPLIT - 1);
    const int rest   = bi >> 2;
    const int chunkq = rest & (QCH - 1);         // 32 query chunks
    const int qset   = rest >> 5;                // 8 sets
    const int cset   = qset ^ 1;

    // ---- this thread's two queries (morton-sorted order) ----
    const int slot0 = chunkq * QPB + tid;
    const int slot1 = slot0 + KT;
    const float q0x = g_px[qset][slot0], q1x = g_px[qset][slot1];
    const float q0y = g_py[qset][slot0], q1y = g_py[qset][slot1];
    const float q0z = g_pz[qset][slot0], q1z = g_pz[qset][slot1];
    const ull qx2 = pack2(q0x, q1x);
    const ull qy2 = pack2(q0y, q1y);
    const ull qz2 = pack2(q0z, q1z);

    const float* __restrict__ cx = g_px[cset];
    const float* __restrict__ cy = g_py[cset];
    const float* __restrict__ cz = g_pz[cset];

    float h0[KNN], h1[KNN];
#pragma unroll
    for (int i = 0; i < KNN; ++i) { h0[i] = 3.0e38f; h1[i] = 3.0e38f; }
    unsigned t0 = __float_as_uint(3.0e38f);
    unsigned t1 = t0;

    for (int ch = 0; ch < NCHUNK; ++ch) {
        __syncthreads();   // previous tile fully consumed
        const int base = split * CANDS + ch * CHUNK;
        // coalesced float4 SoA loads -> packed negated tile
        for (int t = tid; t < CHUNK / 4; t += KT) {      // 2 iterations
            const float4 vx = reinterpret_cast<const float4*>(cx + base)[t];
            const float4 vy = reinterpret_cast<const float4*>(cy + base)[t];
            const float4 vz = reinterpret_cast<const float4*>(cz + base)[t];
            const int p = 4 * t;
            sXY[p + 0].x = dupf(-vx.x); sXY[p + 0].y = dupf(-vy.x); sZ[p + 0] = dupf(-vz.x);
            sXY[p + 1].x = dupf(-vx.y); sXY[p + 1].y = dupf(-vy.y); sZ[p + 1] = dupf(-vz.y);
            sXY[p + 2].x = dupf(-vx.z); sXY[p + 2].y = dupf(-vy.z); sZ[p + 2] = dupf(-vz.z);
            sXY[p + 3].x = dupf(-vx.w); sXY[p + 3].y = dupf(-vy.w); sZ[p + 3] = dupf(-vz.w);
        }
        __syncthreads();

#pragma unroll 4
        for (int j = 0; j < CHUNK; ++j) {
            const ulonglong2 cxy = sXY[j];    // broadcast LDS.128 (pre-negated)
            const ull czz = sZ[j];            // broadcast LDS.64
            const ull dx = fx2_add(qx2, cxy.x);
            const ull dy = fx2_add(qy2, cxy.y);
            const ull dz = fx2_add(qz2, czz);
            const ull d2 = fx2_fma(dx, dx, fx2_fma(dy, dy, fx2_mul(dz, dz)));
            const unsigned d0 = (unsigned)d2;          // query 0
            const unsigned d1 = (unsigned)(d2 >> 32);  // query 1
            // nonnegative floats: uint compare == float compare (alu pipe)
            if (__builtin_expect(d0 < t0, 0)) {
                float v = __uint_as_float(d0);
#pragma unroll
                for (int i = KNN - 1; i > 0; --i) {
                    const float hp = h0[i - 1];
                    h0[i] = fmaxf(hp, v);
                    v     = fminf(hp, v);
                }
                h0[0] = v;
                t0 = __float_as_uint(h0[KNN - 1]);
            }
            if (__builtin_expect(d1 < t1, 0)) {
                float v = __uint_as_float(d1);
#pragma unroll
                for (int i = KNN - 1; i > 0; --i) {
                    const float hp = h1[i - 1];
                    h1[i] = fmaxf(hp, v);
                    v     = fminf(hp, v);
                }
                h1[0] = v;
                t1 = __float_as_uint(h1[KNN - 1]);
            }
        }
    }

    // ---- write per-split sorted partial lists (d^2, ascending) ----
    const int qg0 = qset * N_ + slot0;
    const int qg1 = qset * N_ + slot1;
    float4* o0 = reinterpret_cast<float4*>(&g_knn[split][qg0][0]);
    float4* o1 = reinterpret_cast<float4*>(&g_knn[split][qg1][0]);
    o0[0] = make_float4(h0[0], h0[1], h0[2], h0[3]);
    o0[1] = make_float4(h0[4], h0[5], h0[6], h0[7]);
    o1[0] = make_float4(h1[0], h1[1], h1[2], h1[3]);
    o1[1] = make_float4(h1[4], h1[5], h1[6], h1[7]);
}

// --- exact branchless merge helpers ---
__device__ __forceinline__ void halver8(const float* __restrict__ a,
                                        const float* __restrict__ b,
                                        float* __restrict__ m)
{
#pragma unroll
    for (int i = 0; i < 8; ++i) m[i] = fminf(a[i], b[7 - i]);
}
__device__ __forceinline__ void bitonic_sort8(float* __restrict__ m)
{
#pragma unroll
    for (int st = 4; st > 0; st >>= 1)
#pragma unroll
        for (int i = 0; i < 8; ++i)
            if ((i & st) == 0) {
                const float lo = fminf(m[i], m[i + st]);
                const float hi = fmaxf(m[i], m[i + st]);
                m[i] = lo; m[i + st] = hi;
            }
}

// Merge 4 sorted partial top-8 lists per query, sum sqrt, deterministic reduce.
__global__ __launch_bounds__(256)
void chamfer_merge_kernel()
{
    const int qg = blockIdx.x * 256 + threadIdx.x;
    float L[NSPLIT][KNN];
#pragma unroll
    for (int sp = 0; sp < NSPLIT; ++sp) {
        const float4* p = reinterpret_cast<const float4*>(&g_knn[sp][qg][0]);
        const float4 v0 = p[0], v1 = p[1];
        L[sp][0] = v0.x; L[sp][1] = v0.y; L[sp][2] = v0.z; L[sp][3] = v0.w;
        L[sp][4] = v1.x; L[sp][5] = v1.y; L[sp][6] = v1.z; L[sp][7] = v1.w;
    }

    float m01[8], m23[8], fin[8];
    halver8(L[0], L[1], m01); bitonic_sort8(m01);
    halver8(L[2], L[3], m23); bitonic_sort8(m23);
    halver8(m01, m23, fin);   // 8 smallest of all 32 (multiset)

    float s = 0.0f;
#pragma unroll
    for (int i = 0; i < 8; ++i) s += sqrtf(fin[i]);

#pragma unroll
    for (int o = 16; o > 0; o >>= 1)
        s += __shfl_down_sync(0xffffffffu, s, o);

    __shared__ float ws[8];
    if ((threadIdx.x & 31) == 0) ws[threadIdx.x >> 5] = s;
    __syncthreads();
    if (threadIdx.x == 0) {
        float t = 0.0f;
#pragma unroll
        for (int i = 0; i < 8; ++i) t += ws[i];
        g_partials[blockIdx.x] = t;
    }
}

// ---------- final deterministic reduction ----------------------------------
__global__ __launch_bounds__(MBLOCKS)
void reduce_kernel(float* __restrict__ out)
{
    const int t = threadIdx.x;
    float v = g_partials[t];
#pragma unroll
    for (int o = 16; o > 0; o >>= 1)
        v += __shfl_down_sync(0xffffffffu, v, o);

    __shared__ float ws[MBLOCKS / 32];
    if ((t & 31) == 0) ws[t >> 5] = v;
    __syncthreads();
    if (t == 0) {
        float s = 0.0f;
#pragma unroll
        for (int i = 0; i < MBLOCKS / 32; ++i) s += ws[i];
        out[0] = s * (1.0f / (float)(B_ * N_ * KNN));
    }
}

extern "C" void kernel_launch(void* const* d_in, const int* in_sizes, int n_in,
                              void* d_out, int out_size)
{
    (void)in_sizes; (void)n_in; (void)out_size;
    const float* src  = (const float*)d_in[0];
    const float* tgt  = (const float*)d_in[1];
    const float* flow = (const float*)d_in[2];
    float* out = (float*)d_out;

    bucket_sort_kernel<<<NSETS, 1024>>>(src, tgt, flow);
    knn_kernel<<<KBLK, KT>>>();
    chamfer_merge_kernel<<<MBLOCKS, 256>>>();
    reduce_kernel<<<1, MBLOCKS>>>(out);
}

// round 17
// speedup vs baseline: 1.1915x; 1.0305x over previous
#include <cuda_runtime.h>
#include <math.h>

// ChamferLoss: B=4, N=8192, K=8 nearest neighbors, L2 norm.
// loss = mean over all (query, knn) exact distances, both directions.
//
// R17 = R16 engine (Morton counting sort, QPT=2 f32x2, 1024 blocks = 27.7
//       warps/SM, exact 4-way merge)
//     + interleaved candidate splits (mod 4) with rank-aligned chunk FIRST
//     + EXACT per-chunk bbox pruning (bboxes computed in sort kernel tail;
//       skip chunk when boxdist^2(query bbox, chunk bbox) >= block max h[7]).

namespace {
constexpr int   B_     = 4;
constexpr int   N_     = 8192;
constexpr int   KNN    = 8;
constexpr int   NSETS  = B_ * 2;             // b*2+s: s=0 pred(src+flow), s=1 tgt
constexpr int   NBUCK  = 512;                // 9-bit morton buckets
constexpr int   KT     = 128;                // knn threads
constexpr int   QPT    = 2;                  // queries per thread
constexpr int   QPB    = KT * QPT;           // 256 queries per block
constexpr int   QCH    = N_ / QPB;           // 32 query chunks per set
constexpr int   NSPLIT = 4;                  // candidate index mod 4
constexpr int   GCH    = 1024;               // global candidates per chunk
constexpr int   NCH    = N_ / GCH;           // 8 chunks
constexpr int   SPC    = GCH / NSPLIT;       // 256 split-cands per chunk
constexpr int   KBLK   = NSETS * QCH * NSPLIT;  // 1024 knn blocks
constexpr int   NQTOT  = NSETS * N_;         // 65536 query slots
constexpr int   MBLOCKS = NQTOT / 256;       // 256 merge blocks
}

typedef unsigned long long ull;

__device__ __forceinline__ ull fx2_add(ull a, ull b) {
    ull r; asm("add.rn.f32x2 %0, %1, %2;" : "=l"(r) : "l"(a), "l"(b)); return r;
}
__device__ __forceinline__ ull fx2_mul(ull a, ull b) {
    ull r; asm("mul.rn.f32x2 %0, %1, %2;" : "=l"(r) : "l"(a), "l"(b)); return r;
}
__device__ __forceinline__ ull fx2_fma(ull a, ull b, ull c) {
    ull r; asm("fma.rn.f32x2 %0, %1, %2, %3;" : "=l"(r) : "l"(a), "l"(b), "l"(c)); return r;
}
__device__ __forceinline__ ull pack2(float lo, float hi) {
    return (ull)__float_as_uint(lo) | ((ull)__float_as_uint(hi) << 32);
}
__device__ __forceinline__ ull dupf(float v) {
    unsigned u = __float_as_uint(v);
    return (ull)u | ((ull)u << 32);
}
// 3-bit quantizer over [-4,4) and 9-bit Morton interleave
__device__ __forceinline__ unsigned quant3(float x) {
    float q = (x + 4.0f);                        // cell = 1.0
    q = fminf(fmaxf(q, 0.0f), 7.0f);
    return (unsigned)q;
}
__device__ __forceinline__ unsigned morton9(float x, float y, float z) {
    const unsigned qx = quant3(x), qy = quant3(y), qz = quant3(z);
    unsigned k = 0;
#pragma unroll
    for (int b = 2; b >= 0; --b)
        k = (k << 3) | (((qx >> b) & 1u) << 2) | (((qy >> b) & 1u) << 1) | ((qz >> b) & 1u);
    return k;                                    // 9 bits
}

// Scratch (static device globals: no allocation).
__device__ float g_px[NSETS][N_];        // morton-bucket-sorted coords, SoA
__device__ float g_py[NSETS][N_];
__device__ float g_pz[NSETS][N_];
__device__ float g_bblo[NSETS][NCH][3];  // exact bbox per rank-chunk
__device__ float g_bbhi[NSETS][NCH][3];
__device__ float g_knn[NSPLIT][NQTOT][KNN];  // per-split sorted partial d^2
__device__ float g_partials[MBLOCKS];

// ---------- deterministic counting sort by Morton bucket + chunk bboxes ----
__global__ __launch_bounds__(1024)
void bucket_sort_kernel(const float* __restrict__ src,
                        const float* __restrict__ tgt,
                        const float* __restrict__ flow)
{
    __shared__ unsigned short wcnt[32][NBUCK];   // per-warp per-bucket (32 KB)
    __shared__ unsigned       bstart[NBUCK];
    __shared__ unsigned       tot[NBUCK];
    __shared__ float          rbuf[32];

    const int set = blockIdx.x;
    const int b   = set >> 1;
    const int s   = set & 1;
    const float* __restrict__ sb = src  + (size_t)b * N_ * 3;
    const float* __restrict__ tb = tgt  + (size_t)b * N_ * 3;
    const float* __restrict__ fb = flow + (size_t)b * N_ * 3;

    const int tid  = threadIdx.x;
    const int w    = tid >> 5;
    const int lane = tid & 31;
    const unsigned below = (1u << lane) - 1u;

    for (int i = tid; i < 32 * NBUCK; i += 1024)
        (&wcnt[0][0])[i] = 0;
    __syncthreads();

    // pass 1: count (leader-per-key non-atomic adds; order fixed)
    float xr[8], yr[8], zr[8];
    int   kr[8];
#pragma unroll
    for (int it = 0; it < 8; ++it) {
        const int i = it * 1024 + tid;
        float x, y, z;
        if (s == 0) {
            x = sb[3 * i + 0] + fb[3 * i + 0];
            y = sb[3 * i + 1] + fb[3 * i + 1];
            z = sb[3 * i + 2] + fb[3 * i + 2];
        } else {
            x = tb[3 * i + 0]; y = tb[3 * i + 1]; z = tb[3 * i + 2];
        }
        xr[it] = x; yr[it] = y; zr[it] = z;
        const int key = (int)morton9(x, y, z);
        kr[it] = key;
        const unsigned mask = __match_any_sync(0xffffffffu, key);
        if ((mask & below) == 0u)   // leader lane for this key
            wcnt[w][key] = (unsigned short)(wcnt[w][key] + __popc(mask));
        __syncwarp();
    }
    __syncthreads();

    // per-bucket exclusive scan over warps (thread t owns bucket t)
    unsigned mytot = 0;
    if (tid < NBUCK) {
        unsigned run = 0;
        for (int ww = 0; ww < 32; ++ww) {
            const unsigned c = wcnt[ww][tid];
            wcnt[ww][tid] = (unsigned short)run;
            run += c;
        }
        tot[tid] = run; mytot = run;
    }
    __syncthreads();
    // inclusive scan of bucket totals
    for (int d = 1; d < NBUCK; d <<= 1) {
        unsigned v = 0;
        if (tid < NBUCK && tid >= d) v = tot[tid - d];
        __syncthreads();
        if (tid < NBUCK) tot[tid] += v;
        __syncthreads();
    }
    if (tid < NBUCK) bstart[tid] = tot[tid] - mytot;
    __syncthreads();

    // pass 2: deterministic scatter (per-warp cursors, lane-rank within key)
#pragma unroll
    for (int it = 0; it < 8; ++it) {
        const int key = kr[it];
        const unsigned mask = __match_any_sync(0xffffffffu, key);
        const unsigned r = __popc(mask & below);
        const unsigned basec = wcnt[w][key];
        __syncwarp();
        if (r == 0) wcnt[w][key] = (unsigned short)(basec + __popc(mask));
        __syncwarp();
        const unsigned pos = bstart[key] + basec + r;
        g_px[set][pos] = xr[it];
        g_py[set][pos] = yr[it];
        g_pz[set][pos] = zr[it];
    }
    __syncthreads();   // global writes by this block ordered before re-reads

    // ---- tail: exact bbox of each rank-chunk (1024 points per chunk) ----
    for (int c = 0; c < NCH; ++c) {
        const int i = c * GCH + tid;              // 1024 threads cover chunk
        const float x = g_px[set][i];
        const float y = g_py[set][i];
        const float z = g_pz[set][i];
        float v[6] = { x, y, z, -x, -y, -z };     // min of -v == max of v
#pragma unroll
        for (int q = 0; q < 6; ++q) {
            float u = v[q];
#pragma unroll
            for (int o = 16; o > 0; o >>= 1)
                u = fminf(u, __shfl_xor_sync(0xffffffffu, u, o));
            __syncthreads();
            if (lane == 0) rbuf[w] = u;
            __syncthreads();
            if (tid == 0) {
                float m = rbuf[0];
#pragma unroll
                for (int i2 = 1; i2 < 32; ++i2) m = fminf(m, rbuf[i2]);
                if (q < 3) g_bblo[set][c][q] = m;
                else       g_bbhi[set][c][q - 3] = -m;
            }
        }
    }
}

// ---------- exact bbox-pruned KNN, interleaved splits, c0 first ------------
__global__ __launch_bounds__(KT)
void knn_kernel()
{
    __shared__ __align__(16) ulonglong2 sXY[SPC];  // {-x,-x,-y,-y} (4 KB)
    __shared__ __align__(16) ull        sZ[SPC];   // {-z,-z}        (2 KB)
    __shared__ float swred[KT / 32];
    __shared__ float sql[3][KT / 32], sqh[3][KT / 32];
    __shared__ float sclo[NCH][3], schi[NCH][3];

    const int tid    = threadIdx.x;
    const int lane   = tid & 31;
    const int wib    = tid >> 5;
    const int bi     = blockIdx.x;
    const int split  = bi & (NSPLIT - 1);
    const int rest   = bi >> 2;
    const int chunkq = rest & (QCH - 1);         // 32 query chunks
    const int qset   = rest >> 5;                // 8 sets
    const int cset   = qset ^ 1;

    // ---- this thread's two queries (morton-sorted order) ----
    const int slot0 = chunkq * QPB + tid;
    const int slot1 = slot0 + KT;
    const float q0x = g_px[qset][slot0], q1x = g_px[qset][slot1];
    const float q0y = g_py[qset][slot0], q1y = g_py[qset][slot1];
    const float q0z = g_pz[qset][slot0], q1z = g_pz[qset][slot1];
    const ull qx2 = pack2(q0x, q1x);
    const ull qy2 = pack2(q0y, q1y);
    const ull qz2 = pack2(q0z, q1z);

    // ---- block query bbox ----
    {
        float l[3] = { fminf(q0x, q1x), fminf(q0y, q1y), fminf(q0z, q1z) };
        float hh[3] = { fmaxf(q0x, q1x), fmaxf(q0y, q1y), fmaxf(q0z, q1z) };
#pragma unroll
        for (int q = 0; q < 3; ++q) {
            float lo = l[q], hi = hh[q];
#pragma unroll
            for (int o = 16; o > 0; o >>= 1) {
                lo = fminf(lo, __shfl_xor_sync(0xffffffffu, lo, o));
                hi = fmaxf(hi, __shfl_xor_sync(0xffffffffu, hi, o));
            }
            if (lane == 0) { sql[q][wib] = lo; sqh[q][wib] = hi; }
        }
    }
    // chunk bboxes -> smem
    if (tid < NCH * 3) {
        sclo[tid / 3][tid % 3] = g_bblo[cset][tid / 3][tid % 3];
        schi[tid / 3][tid % 3] = g_bbhi[cset][tid / 3][tid % 3];
    }
    __syncthreads();
    float qlo[3], qhi[3];
#pragma unroll
    for (int q = 0; q < 3; ++q) {
        qlo[q] = fminf(fminf(sql[q][0], sql[q][1]), fminf(sql[q][2], sql[q][3]));
        qhi[q] = fmaxf(fmaxf(sqh[q][0], sqh[q][1]), fmaxf(sqh[q][2], sqh[q][3]));
    }

    const float* __restrict__ cx = g_px[cset];
    const float* __restrict__ cy = g_py[cset];
    const float* __restrict__ cz = g_pz[cset];

    float h0[KNN], h1[KNN];
#pragma unroll
    for (int i = 0; i < KNN; ++i) { h0[i] = 3.0e38f; h1[i] = 3.0e38f; }
    unsigned t0 = __float_as_uint(3.0e38f);
    unsigned t1 = t0;

    auto scan_tile = [&](int c) {
        __syncthreads();                          // previous tile consumed
        const int base = c * GCH + split;
        for (int t = tid; t < SPC; t += KT) {     // 2 iters, stride-4 gather
            const int gi = base + 4 * t;
            sXY[t].x = dupf(-cx[gi]);
            sXY[t].y = dupf(-cy[gi]);
            sZ[t]    = dupf(-cz[gi]);
        }
        __syncthreads();
#pragma unroll 4
        for (int j = 0; j < SPC; ++j) {
            const ulonglong2 cxy = sXY[j];        // broadcast LDS.128
            const ull czz = sZ[j];                // broadcast LDS.64
            const ull dx = fx2_add(qx2, cxy.x);
            const ull dy = fx2_add(qy2, cxy.y);
            const ull dz = fx2_add(qz2, czz);
            const ull d2 = fx2_fma(dx, dx, fx2_fma(dy, dy, fx2_mul(dz, dz)));
            const unsigned d0 = (unsigned)d2;          // query 0
            const unsigned d1 = (unsigned)(d2 >> 32);  // query 1
            if (__builtin_expect(d0 < t0, 0)) {
                float v = __uint_as_float(d0);
#pragma unroll
                for (int i = KNN - 1; i > 0; --i) {
                    const float hp = h0[i - 1];
                    h0[i] = fmaxf(hp, v);
                    v     = fminf(hp, v);
                }
                h0[0] = v;
                t0 = __float_as_uint(h0[KNN - 1]);
            }
            if (__builtin_expect(d1 < t1, 0)) {
                float v = __uint_as_float(d1);
#pragma unroll
                for (int i = KNN - 1; i > 0; --i) {
                    const float hp = h1[i - 1];
                    h1[i] = fmaxf(hp, v);
                    v     = fminf(hp, v);
                }
                h1[0] = v;
                t1 = __float_as_uint(h1[KNN - 1]);
            }
        }
    };

    // 1) rank-aligned chunk first (queries and candidates share Morton space)
    const int c0 = chunkq >> 2;                   // 32 query chunks -> 8 chunks
    scan_tile(c0);

    // 2) remaining chunks with exact bbox skip (block-uniform predicates)
    for (int t = 0; t < NCH; ++t) {
        if (t == c0) continue;
        // block-max current 8th distance (shrinks monotonically)
        float t8 = fmaxf(__uint_as_float(t0), __uint_as_float(t1));
#pragma unroll
        for (int o = 16; o > 0; o >>= 1)
            t8 = fmaxf(t8, __shfl_xor_sync(0xffffffffu, t8, o));
        __syncthreads();                          // swred free
        if (lane == 0) swred[wib] = t8;
        __syncthreads();
        const float tmax = fmaxf(fmaxf(swred[0], swred[1]),
                                 fmaxf(swred[2], swred[3]));
        // exact box-box squared distance
        float d2b = 0.0f;
#pragma unroll
        for (int q = 0; q < 3; ++q) {
            const float g = fmaxf(0.0f, fmaxf(sclo[t][q] - qhi[q], qlo[q] - schi[t][q]));
            d2b = fmaf(g, g, d2b);
        }
        if (d2b < tmax) scan_tile(t);             // skip is provably safe
    }

    // ---- write per-split sorted partial lists (d^2, ascending) ----
    const int qg0 = qset * N_ + slot0;
    const int qg1 = qset * N_ + slot1;
    float4* o0 = reinterpret_cast<float4*>(&g_knn[split][qg0][0]);
    float4* o1 = reinterpret_cast<float4*>(&g_knn[split][qg1][0]);
    o0[0] = make_float4(h0[0], h0[1], h0[2], h0[3]);
    o0[1] = make_float4(h0[4], h0[5], h0[6], h0[7]);
    o1[0] = make_float4(h1[0], h1[1], h1[2], h1[3]);
    o1[1] = make_float4(h1[4], h1[5], h1[6], h1[7]);
}

// --- exact branchless merge helpers ---
__device__ __forceinline__ void halver8(const float* __restrict__ a,
                                        const float* __restrict__ b,
                                        float* __restrict__ m)
{
#pragma unroll
    for (int i = 0; i < 8; ++i) m[i] = fminf(a[i], b[7 - i]);
}
__device__ __forceinline__ void bitonic_sort8(float* __restrict__ m)
{
#pragma unroll
    for (int st = 4; st > 0; st >>= 1)
#pragma unroll
        for (int i = 0; i < 8; ++i)
            if ((i & st) == 0) {
                const float lo = fminf(m[i], m[i + st]);
                const float hi = fmaxf(m[i], m[i + st]);
                m[i] = lo; m[i + st] = hi;
            }
}

// Merge 4 sorted partial top-8 lists per query, sum sqrt, deterministic reduce.
__global__ __launch_bounds__(256)
void chamfer_merge_kernel()
{
    const int qg = blockIdx.x * 256 + threadIdx.x;
    float L[NSPLIT][KNN];
#pragma unroll
    for (int sp = 0; sp < NSPLIT; ++sp) {
        const float4* p = reinterpret_cast<const float4*>(&g_knn[sp][qg][0]);
        const float4 v0 = p[0], v1 = p[1];
        L[sp][0] = v0.x; L[sp][1] = v0.y; L[sp][2] = v0.z; L[sp][3] = v0.w;
        L[sp][4] = v1.x; L[sp][5] = v1.y; L[sp][6] = v1.z; L[sp][7] = v1.w;
    }

    float m01[8], m23[8], fin[8];
    halver8(L[0], L[1], m01); bitonic_sort8(m01);
    halver8(L[2], L[3], m23); bitonic_sort8(m23);
    halver8(m01, m23, fin);   // 8 smallest of all 32 (multiset)

    float s = 0.0f;
#pragma unroll
    for (int i = 0; i < 8; ++i) s += sqrtf(fin[i]);

#pragma unroll
    for (int o = 16; o > 0; o >>= 1)
        s += __shfl_down_sync(0xffffffffu, s, o);

    __shared__ float ws[8];
    if ((threadIdx.x & 31) == 0) ws[threadIdx.x >> 5] = s;
    __syncthreads();
    if (threadIdx.x == 0) {
        float t = 0.0f;
#pragma unroll
        for (int i = 0; i < 8; ++i) t += ws[i];
        g_partials[blockIdx.x] = t;
    }
}

// ---------- final deterministic reduction ----------------------------------
__global__ __launch_bounds__(MBLOCKS)
void reduce_kernel(float* __restrict__ out)
{
    const int t = threadIdx.x;
    float v = g_partials[t];
#pragma unroll
    for (int o = 16; o > 0; o >>= 1)
        v += __shfl_down_sync(0xffffffffu, v, o);

    __shared__ float ws[MBLOCKS / 32];
    if ((t & 31) == 0) ws[t >> 5] = v;
    __syncthreads();
    if (t == 0) {
        float s = 0.0f;
#pragma unroll
        for (int i = 0; i < MBLOCKS / 32; ++i) s += ws[i];
        out[0] = s * (1.0f / (float)(B_ * N_ * KNN));
    }
}

extern "C" void kernel_launch(void* const* d_in, const int* in_sizes, int n_in,
                              void* d_out, int out_size)
{
    (void)in_sizes; (void)n_in; (void)out_size;
    const float* src  = (const float*)d_in[0];
    const float* tgt  = (const float*)d_in[1];
    const float* flow = (const float*)d_in[2];
    float* out = (float*)d_out;

    bucket_sort_kernel<<<NSETS, 1024>>>(src, tgt, flow);
    knn_kernel<<<KBLK, KT>>>();
    chamfer_merge_kernel<<<MBLOCKS, 256>>>();
    reduce_kernel<<<1, MBLOCKS>>>(out);
}